// round 12
// baseline (speedup 1.0000x reference)
#include <cuda_runtime.h>
#include <cuda_bf16.h>
#include <cstdint>

// Problem constants
#define BATCH 4
#define CH    128
#define HW    64
#define PQ    4096            // HW*HW
#define SCALE 10.0f
#define EPS_SUM 0.1152f       // 128*3*3*1e-4
#define LOG2E 1.4426950408889634f
#define KTOT  384             // split-bf16 packed K (ah|al|ah vs bh|bh|bl)
#define BKP   32              // bf16 K per pipeline stage
#define NKIT  (KTOT / BKP)    // 12 stages
#define LDT   40              // padded smem row length (bf16)
#define STAGE_BYTES (2 * 128 * LDT * 2)   // one stage (A+B)  = 20480 B
#define BREG_OFF    (128 * LDT * 2)       // B region within a stage = 10240 B

// ---------------- static scratch ----------------
__device__ float g_G[(size_t)BATCH * PQ * PQ];   // Gt[b][p][q]  (256 MB)
__device__ float g_ssq[BATCH * PQ];
__device__ float g_coef[BATCH * PQ];
__device__ float g_mm[PQ];
__device__ float g_partial[BATCH * 64 * PQ];
__device__ float g_colsum[BATCH * PQ];
// tile-contiguous pack: [b][kk][p][32] ; chunk kk holds k = kk*32..kk*32+31
__device__ __nv_bfloat16 g_Apack[(size_t)BATCH * NKIT * PQ * 32];
__device__ __nv_bfloat16 g_Bpack[(size_t)BATCH * NKIT * PQ * 32];

// ---------------- helpers ----------------
__device__ __forceinline__ uint32_t smem_u32(const void* p) {
    uint32_t a;
    asm("{ .reg .u64 t; cvta.to.shared.u64 t, %1; cvt.u32.u64 %0, t; }" : "=r"(a) : "l"(p));
    return a;
}
__device__ __forceinline__ void cpa16(void* dst, const void* src) {
    asm volatile("cp.async.cg.shared.global [%0], [%1], 16;"
                 :: "r"(smem_u32(dst)), "l"(src));
}
#define CP_COMMIT() asm volatile("cp.async.commit_group;" ::: "memory")
#define CP_WAIT(n)  asm volatile("cp.async.wait_group %0;" :: "n"(n) : "memory")

__device__ __forceinline__ void ldsm_x4(uint32_t* r, uint32_t addr) {
    asm volatile("ldmatrix.sync.aligned.m8n8.x4.shared.b16 {%0,%1,%2,%3}, [%4];"
                 : "=r"(r[0]), "=r"(r[1]), "=r"(r[2]), "=r"(r[3]) : "r"(addr));
}
__device__ __forceinline__ void mma16816(float* c, const uint32_t* a, const uint32_t* bfr) {
    asm volatile(
        "mma.sync.aligned.m16n8k16.row.col.f32.bf16.bf16.f32 "
        "{%0,%1,%2,%3}, {%4,%5,%6,%7}, {%8,%9}, {%0,%1,%2,%3};"
        : "+f"(c[0]), "+f"(c[1]), "+f"(c[2]), "+f"(c[3])
        : "r"(a[0]), "r"(a[1]), "r"(a[2]), "r"(a[3]), "r"(bfr[0]), "r"(bfr[1]));
}

// fast 2^t on the FMA pipe (degree-5, rel err ~2.4e-6)
__device__ __forceinline__ float fast_exp2(float t) {
    t = fminf(fmaxf(t, -120.0f), 120.0f);
    float fn = rintf(t);
    float f  = t - fn;
    float p  = 1.3333558e-3f;
    p = fmaf(p, f, 9.6181291e-3f);
    p = fmaf(p, f, 5.5504109e-2f);
    p = fmaf(p, f, 2.4022651e-1f);
    p = fmaf(p, f, 6.9314718e-1f);
    p = fmaf(p, f, 1.0f);
    int n = (int)fn;
    return p * __int_as_float((n + 127) << 23);
}

// ---------------- K-1: split fp32 -> packed bf16 hi/lo (tile-contiguous) ------------
__global__ void k_split(const float* __restrict__ fin, const float* __restrict__ bin) {
    __shared__ float tile[32][33];
    int z = blockIdx.z;
    int isA = (z < BATCH);
    int b = isA ? z : z - BATCH;
    const float* src = (isA ? bin : fin) + (size_t)b * CH * PQ;
    __nv_bfloat16* dst = (isA ? g_Apack : g_Bpack) + (size_t)b * NKIT * PQ * 32;

    int p0 = blockIdx.x * 32, c0 = blockIdx.y * 32;
    int kk0 = c0 >> 5;                       // hi chunk index; mid = +4, far = +8
    int tx = threadIdx.x, ty = threadIdx.y;  // (32, 8)
#pragma unroll
    for (int j = 0; j < 4; j++)
        tile[ty + 8 * j][tx] = src[(size_t)(c0 + ty + 8 * j) * PQ + p0 + tx];
    __syncthreads();
    const size_t CHK = (size_t)PQ * 32;      // elements per kk chunk
#pragma unroll
    for (int j = 0; j < 4; j++) {
        int r = ty + 8 * j;
        float a = tile[tx][r];               // channel c0+tx, pixel p0+r
        __nv_bfloat16 hi = __float2bfloat16_rn(a);
        __nv_bfloat16 lo = __float2bfloat16_rn(a - __bfloat162float(hi));
        size_t poff = (size_t)(p0 + r) * 32 + tx;
        dst[(size_t)kk0 * CHK + poff]        = hi;
        dst[(size_t)(kk0 + 4) * CHK + poff]  = isA ? lo : hi;
        dst[(size_t)(kk0 + 8) * CHK + poff]  = isA ? hi : lo;
    }
}

// ---------------- K0a: ssq[b,p] = sum_c b[b,c,p]^2 ----------------
__global__ void k_ssq(const float* __restrict__ bin) {
    int p = blockIdx.x * 256 + threadIdx.x;
    int b = blockIdx.y;
    const float* src = bin + ((size_t)b * CH) * PQ + p;
    float s = 0.f;
#pragma unroll 8
    for (int c = 0; c < CH; c++) {
        float v = src[(size_t)c * PQ];
        s += v * v;
    }
    g_ssq[b * PQ + p] = s;
}

// ---------------- K0b: coef ----------------
__global__ void k_prep(const float* __restrict__ mask) {
    int p = blockIdx.x * 256 + threadIdx.x;
    int b = blockIdx.y;
    int py = p >> 6, px = p & 63;

    float s = EPS_SUM;
    bool masked = false;
#pragma unroll
    for (int dy = -1; dy <= 1; dy++) {
#pragma unroll
        for (int dx = -1; dx <= 1; dx++) {
            int yy = py + dy, xx = px + dx;
            if ((unsigned)yy < 64u && (unsigned)xx < 64u) {
                s += g_ssq[b * PQ + (yy << 6) + xx];
                if (mask[(size_t)(yy * 8) * 512 + xx * 8] != 0.0f) masked = true;
            }
        }
    }
    g_coef[b * PQ + p] = masked ? 0.0f : (SCALE * LOG2E / sqrtf(s));
    if (b == 0) g_mm[p] = masked ? 0.0f : 1.0f;
}

// ---------------- K1: HMMA bf16-split GEMM  Gt[p][q] = A.B (64x64 warp tile) -------
// CTA 128x128, K=384, BK=32, 128 thr = 4 warps (2 m x 2 n), warp tile 64x64.
// Tile-contiguous pack -> dense 8KB stage fills; shfl-paired float4 epilogue.
__global__ __launch_bounds__(128, 2) void k_gemm_mma() {
    __shared__ __align__(16) __nv_bfloat16 sm[2][2][128][LDT];  // [stage][A/B][row][k]
    uint32_t sbase = smem_u32(&sm[0][0][0][0]);

    int tid = threadIdx.x;
    int wid = tid >> 5, lid = tid & 31;
    int g = lid >> 2, tig = lid & 3;
    int warp_m = wid & 1, warp_n = wid >> 1;

    int b  = blockIdx.z;
    int m0 = blockIdx.y * 128;   // p
    int n0 = blockIdx.x * 128;   // q
    const size_t CHK = (size_t)PQ * 32;
    const __nv_bfloat16* Ap = g_Apack + (size_t)b * NKIT * CHK + (size_t)m0 * 32;
    const __nv_bfloat16* Bp = g_Bpack + (size_t)b * NKIT * CHK + (size_t)n0 * 32;

    float acc[4][8][4];
#pragma unroll
    for (int mt = 0; mt < 4; mt++)
#pragma unroll
        for (int nt = 0; nt < 8; nt++)
#pragma unroll
            for (int i = 0; i < 4; i++) acc[mt][nt][i] = 0.f;

    // ldmatrix per-lane byte offsets within a stage
    uint32_t a_off[4];
#pragma unroll
    for (int mt = 0; mt < 4; mt++) {
        int row = warp_m * 64 + mt * 16 + (lid & 15);
        int kof = (lid >> 4) * 8;
        a_off[mt] = (uint32_t)((row * LDT + kof) * 2);
    }
    uint32_t b_off[4];
#pragma unroll
    for (int ntp = 0; ntp < 4; ntp++) {
        int row = warp_n * 64 + ntp * 16 + (lid & 7) + ((lid >> 4) << 3);
        int kof = ((lid >> 3) & 1) * 8;
        b_off[ntp] = (uint32_t)(BREG_OFF + (row * LDT + kof) * 2);
    }

    // dense stage fill: 512 x 16B chunks per operand; thread handles ci = tid + i*128
    // ci -> smem row = ci>>2, byte col = (ci&3)*16 ; gmem fully contiguous
#pragma unroll
    for (int i = 0; i < 4; i++) {
        int ci = tid + i * 128;
        cpa16((char*)&sm[0][0][0][0] + (ci >> 2) * (LDT * 2) + (ci & 3) * 16, Ap + (size_t)ci * 8);
        cpa16((char*)&sm[0][1][0][0] + (ci >> 2) * (LDT * 2) + (ci & 3) * 16, Bp + (size_t)ci * 8);
    }
    CP_COMMIT();

#pragma unroll 1
    for (int kk = 0; kk < NKIT; kk++) {
        if (kk + 1 < NKIT) {
            int st = (kk + 1) & 1;
            const __nv_bfloat16* An = Ap + (size_t)(kk + 1) * CHK;
            const __nv_bfloat16* Bn = Bp + (size_t)(kk + 1) * CHK;
#pragma unroll
            for (int i = 0; i < 4; i++) {
                int ci = tid + i * 128;
                cpa16((char*)&sm[st][0][0][0] + (ci >> 2) * (LDT * 2) + (ci & 3) * 16, An + (size_t)ci * 8);
                cpa16((char*)&sm[st][1][0][0] + (ci >> 2) * (LDT * 2) + (ci & 3) * 16, Bn + (size_t)ci * 8);
            }
            CP_COMMIT();
            CP_WAIT(1);
        } else {
            CP_WAIT(0);
        }
        __syncthreads();

        uint32_t stg = sbase + (uint32_t)(kk & 1) * STAGE_BYTES;
#pragma unroll
        for (int ks = 0; ks < 2; ks++) {
            uint32_t kadj = (uint32_t)(ks * 32);   // 16 bf16 = 32 B
            uint32_t afr[4][4];
#pragma unroll
            for (int mt = 0; mt < 4; mt++) ldsm_x4(afr[mt], stg + a_off[mt] + kadj);
            uint32_t bfr[4][4];
#pragma unroll
            for (int ntp = 0; ntp < 4; ntp++) ldsm_x4(bfr[ntp], stg + b_off[ntp] + kadj);
#pragma unroll
            for (int mt = 0; mt < 4; mt++)
#pragma unroll
                for (int nt = 0; nt < 8; nt++)
                    mma16816(acc[mt][nt], afr[mt], &bfr[nt >> 1][(nt & 1) * 2]);
        }
        __syncthreads();
    }

    // epilogue: shfl-pair lanes (tig ^ 1) to build float4, STG.128 (16 contig cols/pair)
    float* Gp = g_G + (size_t)b * PQ * PQ;
    int odd = tig & 1;
#pragma unroll
    for (int mt = 0; mt < 4; mt++) {
        int row = m0 + warp_m * 64 + mt * 16 + g;
#pragma unroll
        for (int ntp = 0; ntp < 4; ntp++) {
            int nt = 2 * ntp;
            // send my float2 of the tile my partner owns; receive mine
            float s0 = odd ? acc[mt][nt][0] : acc[mt][nt + 1][0];
            float s1 = odd ? acc[mt][nt][1] : acc[mt][nt + 1][1];
            float s2 = odd ? acc[mt][nt][2] : acc[mt][nt + 1][2];
            float s3 = odd ? acc[mt][nt][3] : acc[mt][nt + 1][3];
            float r0 = __shfl_xor_sync(0xffffffffu, s0, 1);
            float r1 = __shfl_xor_sync(0xffffffffu, s1, 1);
            float r2 = __shfl_xor_sync(0xffffffffu, s2, 1);
            float r3 = __shfl_xor_sync(0xffffffffu, s3, 1);
            int my = nt + odd;                 // tile this lane stores
            float4 lo = odd ? make_float4(r0, r1, acc[mt][my][0], acc[mt][my][1])
                            : make_float4(acc[mt][my][0], acc[mt][my][1], r0, r1);
            float4 hi = odd ? make_float4(r2, r3, acc[mt][my][2], acc[mt][my][3])
                            : make_float4(acc[mt][my][2], acc[mt][my][3], r2, r3);
            int col = n0 + warp_n * 64 + 8 * my + ((tig >> 1) << 2);
            *(float4*)&Gp[(size_t)row * PQ + col]       = lo;
            *(float4*)&Gp[(size_t)(row + 8) * PQ + col] = hi;
        }
    }
}

// ---------------- K2: 9-tap diagonal sum + exp2 + out + column partials ----------------
__global__ __launch_bounds__(256) void k_sum9(float* __restrict__ out) {
    int b    = blockIdx.z;
    int prow = blockIdx.y;
    int q    = blockIdx.x * 256 + threadIdx.x;
    int qy   = q >> 6, qx = q & 63;

    const float* __restrict__ Gp = g_G + (size_t)b * PQ * PQ;
    const float* __restrict__ cf = g_coef + b * PQ + prow * 64;

    const bool rvm = (prow > 0)  && (qy > 0);
    const bool rvp = (prow < 63) && (qy < 63);
    const bool qlf = (qx > 0), qrt = (qx < 63);

    const float* base = Gp + (size_t)(prow * 64) * PQ + q;
    float* orow = out + ((size_t)(b * PQ + prow * 64)) * PQ + q;
    float partial = 0.f;

#pragma unroll 8
    for (int px = 0; px < 64; px++) {
        bool lf = qlf && (px > 0);
        bool rt = qrt && (px < 63);
        float s = 0.f;
        if (rvm) {
            if (lf) s += __ldg(base - 65 * 4097);
            s += __ldg(base - 64 * 4097);
            if (rt) s += __ldg(base - 63 * 4097);
        }
        if (lf) s += __ldg(base - 4097);
        s += __ldg(base);
        if (rt) s += __ldg(base + 4097);
        if (rvp) {
            if (lf) s += __ldg(base + 63 * 4097);
            s += __ldg(base + 64 * 4097);
            if (rt) s += __ldg(base + 65 * 4097);
        }
        float e = fast_exp2(s * cf[px]);
        __stcs(orow, e);
        partial += e;
        base += PQ;
        orow += PQ;
    }
    g_partial[((size_t)(b * 64 + prow)) * PQ + q] = partial;
}

// ---------------- K2b: deterministic reduction of column partials ----------------
__global__ void k_colreduce() {
    int q = blockIdx.x * 256 + threadIdx.x;
    int b = blockIdx.y;
    const float* src = g_partial + (size_t)(b * 64) * PQ + q;
    float s = 0.f;
#pragma unroll 8
    for (int j = 0; j < 64; j++) s += src[(size_t)j * PQ];
    g_colsum[b * PQ + q] = s;
}

// ---------------- K3: normalize ----------------
__global__ void k_norm(float* __restrict__ out) {
    size_t i4  = (size_t)blockIdx.x * 256 + threadIdx.x;
    size_t row = i4 >> 10;
    int p  = (int)(row & 4095);
    int b  = (int)(row >> 12);
    int c4 = (int)(i4 & 1023);

    float4 v  = __ldcs((const float4*)out + i4);
    float  m  = g_mm[p];
    float4 cs = ((const float4*)g_colsum)[b * 1024 + c4];
    v.x = m * v.x / cs.x;
    v.y = m * v.y / cs.y;
    v.z = m * v.z / cs.z;
    v.w = m * v.w / cs.w;
    __stcs((float4*)out + i4, v);
}

// ---------------- launch ----------------
extern "C" void kernel_launch(void* const* d_in, const int* in_sizes, int n_in,
                              void* d_out, int out_size) {
    const float* f    = (const float*)d_in[0];
    const float* bb   = (const float*)d_in[1];
    const float* mask = (const float*)d_in[2];
    float* out = (float*)d_out;

    k_split    <<<dim3(PQ / 32, CH / 32, 2 * BATCH), dim3(32, 8)>>>(f, bb);
    k_ssq      <<<dim3(PQ / 256, BATCH), 256>>>(bb);
    k_prep     <<<dim3(PQ / 256, BATCH), 256>>>(mask);
    k_gemm_mma <<<dim3(PQ / 128, PQ / 128, BATCH), 128>>>();
    k_sum9     <<<dim3(PQ / 256, 64, BATCH), 256>>>(out);
    k_colreduce<<<dim3(PQ / 256, BATCH), 256>>>();
    k_norm     <<<(unsigned)(((size_t)BATCH * PQ * PQ / 4) / 256), 256>>>(out);
}

// round 13
// speedup vs baseline: 2.4422x; 2.4422x over previous
#include <cuda_runtime.h>
#include <cuda_bf16.h>
#include <cstdint>

// Problem constants
#define BATCH 4
#define CH    128
#define HW    64
#define PQ    4096            // HW*HW
#define SCALE 10.0f
#define EPS_SUM 0.1152f       // 128*3*3*1e-4
#define LOG2E 1.4426950408889634f
#define KTOT  384             // split-bf16 packed K (ah|al|ah vs bh|bh|bl)
#define BKP   32              // bf16 K per pipeline stage
#define NKIT  (KTOT / BKP)    // 12 stages
#define LDT   40              // padded smem row length (bf16)
#define STAGE_BYTES (2 * 128 * LDT * 2)   // one stage (A+B)  = 20480 B
#define BREG_OFF    (128 * LDT * 2)       // B region within a stage = 10240 B

// ---------------- static scratch ----------------
__device__ float g_G[(size_t)BATCH * PQ * PQ];   // Gt[b][p][q]  (256 MB)
__device__ float g_ssq[BATCH * PQ];
__device__ float g_coef[BATCH * PQ];
__device__ float g_mm[PQ];
__device__ float g_partial[BATCH * 64 * PQ];
__device__ float g_colsum[BATCH * PQ];
// tile-contiguous pack: [b][kk][p][32] ; chunk kk holds k = kk*32..kk*32+31
__device__ __nv_bfloat16 g_Apack[(size_t)BATCH * NKIT * PQ * 32];
__device__ __nv_bfloat16 g_Bpack[(size_t)BATCH * NKIT * PQ * 32];

// ---------------- helpers ----------------
__device__ __forceinline__ uint32_t smem_u32(const void* p) {
    uint32_t a;
    asm("{ .reg .u64 t; cvta.to.shared.u64 t, %1; cvt.u32.u64 %0, t; }" : "=r"(a) : "l"(p));
    return a;
}
__device__ __forceinline__ void cpa16(void* dst, const void* src) {
    asm volatile("cp.async.cg.shared.global [%0], [%1], 16;"
                 :: "r"(smem_u32(dst)), "l"(src));
}
#define CP_COMMIT() asm volatile("cp.async.commit_group;" ::: "memory")
#define CP_WAIT(n)  asm volatile("cp.async.wait_group %0;" :: "n"(n) : "memory")

__device__ __forceinline__ void ldsm_x4(uint32_t* r, uint32_t addr) {
    asm volatile("ldmatrix.sync.aligned.m8n8.x4.shared.b16 {%0,%1,%2,%3}, [%4];"
                 : "=r"(r[0]), "=r"(r[1]), "=r"(r[2]), "=r"(r[3]) : "r"(addr));
}
__device__ __forceinline__ void mma16816(float* c, const uint32_t* a, const uint32_t* bfr) {
    asm volatile(
        "mma.sync.aligned.m16n8k16.row.col.f32.bf16.bf16.f32 "
        "{%0,%1,%2,%3}, {%4,%5,%6,%7}, {%8,%9}, {%0,%1,%2,%3};"
        : "+f"(c[0]), "+f"(c[1]), "+f"(c[2]), "+f"(c[3])
        : "r"(a[0]), "r"(a[1]), "r"(a[2]), "r"(a[3]), "r"(bfr[0]), "r"(bfr[1]));
}

// fast 2^t on the FMA pipe (degree-5, rel err ~2.4e-6)
__device__ __forceinline__ float fast_exp2(float t) {
    t = fminf(fmaxf(t, -120.0f), 120.0f);
    float fn = rintf(t);
    float f  = t - fn;
    float p  = 1.3333558e-3f;
    p = fmaf(p, f, 9.6181291e-3f);
    p = fmaf(p, f, 5.5504109e-2f);
    p = fmaf(p, f, 2.4022651e-1f);
    p = fmaf(p, f, 6.9314718e-1f);
    p = fmaf(p, f, 1.0f);
    int n = (int)fn;
    return p * __int_as_float((n + 127) << 23);
}

// ---------------- K-1: split fp32 -> packed bf16 hi/lo (tile-contiguous) ------------
__global__ void k_split(const float* __restrict__ fin, const float* __restrict__ bin) {
    __shared__ float tile[32][33];
    int z = blockIdx.z;
    int isA = (z < BATCH);
    int b = isA ? z : z - BATCH;
    const float* src = (isA ? bin : fin) + (size_t)b * CH * PQ;
    __nv_bfloat16* dst = (isA ? g_Apack : g_Bpack) + (size_t)b * NKIT * PQ * 32;

    int p0 = blockIdx.x * 32, c0 = blockIdx.y * 32;
    int kk0 = c0 >> 5;                       // hi chunk index; mid = +4, far = +8
    int tx = threadIdx.x, ty = threadIdx.y;  // (32, 8)
#pragma unroll
    for (int j = 0; j < 4; j++)
        tile[ty + 8 * j][tx] = src[(size_t)(c0 + ty + 8 * j) * PQ + p0 + tx];
    __syncthreads();
    const size_t CHK = (size_t)PQ * 32;      // elements per kk chunk
#pragma unroll
    for (int j = 0; j < 4; j++) {
        int r = ty + 8 * j;
        float a = tile[tx][r];               // channel c0+tx, pixel p0+r
        __nv_bfloat16 hi = __float2bfloat16_rn(a);
        __nv_bfloat16 lo = __float2bfloat16_rn(a - __bfloat162float(hi));
        size_t poff = (size_t)(p0 + r) * 32 + tx;
        dst[(size_t)kk0 * CHK + poff]        = hi;
        dst[(size_t)(kk0 + 4) * CHK + poff]  = isA ? lo : hi;
        dst[(size_t)(kk0 + 8) * CHK + poff]  = isA ? hi : lo;
    }
}

// ---------------- K0a: ssq[b,p] = sum_c b[b,c,p]^2 ----------------
__global__ void k_ssq(const float* __restrict__ bin) {
    int p = blockIdx.x * 256 + threadIdx.x;
    int b = blockIdx.y;
    const float* src = bin + ((size_t)b * CH) * PQ + p;
    float s = 0.f;
#pragma unroll 8
    for (int c = 0; c < CH; c++) {
        float v = src[(size_t)c * PQ];
        s += v * v;
    }
    g_ssq[b * PQ + p] = s;
}

// ---------------- K0b: coef ----------------
__global__ void k_prep(const float* __restrict__ mask) {
    int p = blockIdx.x * 256 + threadIdx.x;
    int b = blockIdx.y;
    int py = p >> 6, px = p & 63;

    float s = EPS_SUM;
    bool masked = false;
#pragma unroll
    for (int dy = -1; dy <= 1; dy++) {
#pragma unroll
        for (int dx = -1; dx <= 1; dx++) {
            int yy = py + dy, xx = px + dx;
            if ((unsigned)yy < 64u && (unsigned)xx < 64u) {
                s += g_ssq[b * PQ + (yy << 6) + xx];
                if (mask[(size_t)(yy * 8) * 512 + xx * 8] != 0.0f) masked = true;
            }
        }
    }
    g_coef[b * PQ + p] = masked ? 0.0f : (SCALE * LOG2E / sqrtf(s));
    if (b == 0) g_mm[p] = masked ? 0.0f : 1.0f;
}

// ---------------- K1: HMMA bf16-split GEMM  Gt[p][q] = A.B (64x64 warp tile) -------
// CTA 128x128, K=384, BK=32, 128 thr = 4 warps (2 m x 2 n), warp tile 64x64.
// Tile-contiguous pack -> dense 8KB stage fills; static-indexed float2 epilogue.
__global__ __launch_bounds__(128, 2) void k_gemm_mma() {
    __shared__ __align__(16) __nv_bfloat16 sm[2][2][128][LDT];  // [stage][A/B][row][k]
    uint32_t sbase = smem_u32(&sm[0][0][0][0]);

    int tid = threadIdx.x;
    int wid = tid >> 5, lid = tid & 31;
    int g = lid >> 2, tig = lid & 3;
    int warp_m = wid & 1, warp_n = wid >> 1;

    int b  = blockIdx.z;
    int m0 = blockIdx.y * 128;   // p
    int n0 = blockIdx.x * 128;   // q
    const size_t CHK = (size_t)PQ * 32;
    const __nv_bfloat16* Ap = g_Apack + (size_t)b * NKIT * CHK + (size_t)m0 * 32;
    const __nv_bfloat16* Bp = g_Bpack + (size_t)b * NKIT * CHK + (size_t)n0 * 32;

    float acc[4][8][4];
#pragma unroll
    for (int mt = 0; mt < 4; mt++)
#pragma unroll
        for (int nt = 0; nt < 8; nt++)
#pragma unroll
            for (int i = 0; i < 4; i++) acc[mt][nt][i] = 0.f;

    // ldmatrix per-lane byte offsets within a stage
    uint32_t a_off[4];
#pragma unroll
    for (int mt = 0; mt < 4; mt++) {
        int row = warp_m * 64 + mt * 16 + (lid & 15);
        int kof = (lid >> 4) * 8;
        a_off[mt] = (uint32_t)((row * LDT + kof) * 2);
    }
    uint32_t b_off[4];
#pragma unroll
    for (int ntp = 0; ntp < 4; ntp++) {
        int row = warp_n * 64 + ntp * 16 + (lid & 7) + ((lid >> 4) << 3);
        int kof = ((lid >> 3) & 1) * 8;
        b_off[ntp] = (uint32_t)(BREG_OFF + (row * LDT + kof) * 2);
    }

    // dense stage fill: 512 x 16B chunks per operand; thread handles ci = tid + i*128
    // ci -> smem row = ci>>2, byte col = (ci&3)*16 ; gmem fully contiguous
#pragma unroll
    for (int i = 0; i < 4; i++) {
        int ci = tid + i * 128;
        cpa16((char*)&sm[0][0][0][0] + (ci >> 2) * (LDT * 2) + (ci & 3) * 16, Ap + (size_t)ci * 8);
        cpa16((char*)&sm[0][1][0][0] + (ci >> 2) * (LDT * 2) + (ci & 3) * 16, Bp + (size_t)ci * 8);
    }
    CP_COMMIT();

#pragma unroll 1
    for (int kk = 0; kk < NKIT; kk++) {
        if (kk + 1 < NKIT) {
            int st = (kk + 1) & 1;
            const __nv_bfloat16* An = Ap + (size_t)(kk + 1) * CHK;
            const __nv_bfloat16* Bn = Bp + (size_t)(kk + 1) * CHK;
#pragma unroll
            for (int i = 0; i < 4; i++) {
                int ci = tid + i * 128;
                cpa16((char*)&sm[st][0][0][0] + (ci >> 2) * (LDT * 2) + (ci & 3) * 16, An + (size_t)ci * 8);
                cpa16((char*)&sm[st][1][0][0] + (ci >> 2) * (LDT * 2) + (ci & 3) * 16, Bn + (size_t)ci * 8);
            }
            CP_COMMIT();
            CP_WAIT(1);
        } else {
            CP_WAIT(0);
        }
        __syncthreads();

        uint32_t stg = sbase + (uint32_t)(kk & 1) * STAGE_BYTES;
#pragma unroll
        for (int ks = 0; ks < 2; ks++) {
            uint32_t kadj = (uint32_t)(ks * 32);   // 16 bf16 = 32 B
            uint32_t afr[4][4];
#pragma unroll
            for (int mt = 0; mt < 4; mt++) ldsm_x4(afr[mt], stg + a_off[mt] + kadj);
            uint32_t bfr[4][4];
#pragma unroll
            for (int ntp = 0; ntp < 4; ntp++) ldsm_x4(bfr[ntp], stg + b_off[ntp] + kadj);
#pragma unroll
            for (int mt = 0; mt < 4; mt++)
#pragma unroll
                for (int nt = 0; nt < 8; nt++)
                    mma16816(acc[mt][nt], afr[mt], &bfr[nt >> 1][(nt & 1) * 2]);
        }
        __syncthreads();
    }

    // epilogue: static-indexed float2 stores (no dynamic acc indexing -> no spills)
    float* Gp = g_G + (size_t)b * PQ * PQ;
#pragma unroll
    for (int mt = 0; mt < 4; mt++) {
        int row = m0 + warp_m * 64 + mt * 16 + g;
#pragma unroll
        for (int nt = 0; nt < 8; nt++) {
            int col = n0 + warp_n * 64 + nt * 8 + tig * 2;
            *(float2*)&Gp[(size_t)row * PQ + col]       = make_float2(acc[mt][nt][0], acc[mt][nt][1]);
            *(float2*)&Gp[(size_t)(row + 8) * PQ + col] = make_float2(acc[mt][nt][2], acc[mt][nt][3]);
        }
    }
}

// ---------------- K2: 9-tap diagonal sum + exp2 + out + column partials ----------------
__global__ __launch_bounds__(256) void k_sum9(float* __restrict__ out) {
    int b    = blockIdx.z;
    int prow = blockIdx.y;
    int q    = blockIdx.x * 256 + threadIdx.x;
    int qy   = q >> 6, qx = q & 63;

    const float* __restrict__ Gp = g_G + (size_t)b * PQ * PQ;
    const float* __restrict__ cf = g_coef + b * PQ + prow * 64;

    const bool rvm = (prow > 0)  && (qy > 0);
    const bool rvp = (prow < 63) && (qy < 63);
    const bool qlf = (qx > 0), qrt = (qx < 63);

    const float* base = Gp + (size_t)(prow * 64) * PQ + q;
    float* orow = out + ((size_t)(b * PQ + prow * 64)) * PQ + q;
    float partial = 0.f;

#pragma unroll 8
    for (int px = 0; px < 64; px++) {
        bool lf = qlf && (px > 0);
        bool rt = qrt && (px < 63);
        float s = 0.f;
        if (rvm) {
            if (lf) s += __ldg(base - 65 * 4097);
            s += __ldg(base - 64 * 4097);
            if (rt) s += __ldg(base - 63 * 4097);
        }
        if (lf) s += __ldg(base - 4097);
        s += __ldg(base);
        if (rt) s += __ldg(base + 4097);
        if (rvp) {
            if (lf) s += __ldg(base + 63 * 4097);
            s += __ldg(base + 64 * 4097);
            if (rt) s += __ldg(base + 65 * 4097);
        }
        float e = fast_exp2(s * cf[px]);
        __stcs(orow, e);
        partial += e;
        base += PQ;
        orow += PQ;
    }
    g_partial[((size_t)(b * 64 + prow)) * PQ + q] = partial;
}

// ---------------- K2b: deterministic reduction of column partials ----------------
__global__ void k_colreduce() {
    int q = blockIdx.x * 256 + threadIdx.x;
    int b = blockIdx.y;
    const float* src = g_partial + (size_t)(b * 64) * PQ + q;
    float s = 0.f;
#pragma unroll 8
    for (int j = 0; j < 64; j++) s += src[(size_t)j * PQ];
    g_colsum[b * PQ + q] = s;
}

// ---------------- K3: normalize ----------------
__global__ void k_norm(float* __restrict__ out) {
    size_t i4  = (size_t)blockIdx.x * 256 + threadIdx.x;
    size_t row = i4 >> 10;
    int p  = (int)(row & 4095);
    int b  = (int)(row >> 12);
    int c4 = (int)(i4 & 1023);

    float4 v  = __ldcs((const float4*)out + i4);
    float  m  = g_mm[p];
    float4 cs = ((const float4*)g_colsum)[b * 1024 + c4];
    v.x = m * v.x / cs.x;
    v.y = m * v.y / cs.y;
    v.z = m * v.z / cs.z;
    v.w = m * v.w / cs.w;
    __stcs((float4*)out + i4, v);
}

// ---------------- launch ----------------
extern "C" void kernel_launch(void* const* d_in, const int* in_sizes, int n_in,
                              void* d_out, int out_size) {
    const float* f    = (const float*)d_in[0];
    const float* bb   = (const float*)d_in[1];
    const float* mask = (const float*)d_in[2];
    float* out = (float*)d_out;

    k_split    <<<dim3(PQ / 32, CH / 32, 2 * BATCH), dim3(32, 8)>>>(f, bb);
    k_ssq      <<<dim3(PQ / 256, BATCH), 256>>>(bb);
    k_prep     <<<dim3(PQ / 256, BATCH), 256>>>(mask);
    k_gemm_mma <<<dim3(PQ / 128, PQ / 128, BATCH), 128>>>();
    k_sum9     <<<dim3(PQ / 256, 64, BATCH), 256>>>(out);
    k_colreduce<<<dim3(PQ / 256, BATCH), 256>>>();
    k_norm     <<<(unsigned)(((size_t)BATCH * PQ * PQ / 4) / 256), 256>>>(out);
}